// round 1
// baseline (speedup 1.0000x reference)
#include <cuda_runtime.h>
#include <cuda_bf16.h>
#include <math_constants.h>

// Problem constants (fixed by the dataset)
#define NN 50000
#define NE 800000
#define ETOT (NE + NN)       // edges + self loops = 850000
#define NG 64
#define HEADS 4

// ---------------- scratch (no cudaMalloc allowed) ----------------
__device__ float g_xl[NN * 128];
__device__ float g_xr[NN * 128];
__device__ float g_h1[NN * 128];
__device__ float g_h2[NN * 64];
__device__ float g_h3[NN * 8];
__device__ int   g_deg[NN];
__device__ int   g_off[NN + 1];
__device__ int   g_cursor[NN];
__device__ int   g_srcs[ETOT];
__device__ int   g_go[NG + 1];

// ---------------- CSR build ----------------
__global__ void zero_deg_kernel() {
    int i = blockIdx.x * blockDim.x + threadIdx.x;
    if (i < NN) g_deg[i] = 0;
}

__global__ void count_deg_kernel(const int* __restrict__ ei) {
    int e = blockIdx.x * blockDim.x + threadIdx.x;
    if (e >= ETOT) return;
    int dst = (e < NE) ? ei[NE + e] : (e - NE);
    atomicAdd(&g_deg[dst], 1);
}

// single-block exclusive scan over g_deg -> g_off, g_cursor
__global__ void scan_kernel() {
    __shared__ int sm[1024];
    __shared__ int carry_s;
    int t = threadIdx.x;
    if (t == 0) carry_s = 0;
    __syncthreads();
    for (int base = 0; base < NN; base += 1024) {
        int i = base + t;
        int v = (i < NN) ? g_deg[i] : 0;
        sm[t] = v;
        __syncthreads();
        for (int ofs = 1; ofs < 1024; ofs <<= 1) {
            int add = (t >= ofs) ? sm[t - ofs] : 0;
            __syncthreads();
            sm[t] += add;
            __syncthreads();
        }
        int excl = carry_s + sm[t] - v;
        if (i < NN) { g_off[i] = excl; g_cursor[i] = excl; }
        __syncthreads();
        if (t == 0) carry_s += sm[1023];
        __syncthreads();
    }
    if (t == 0) g_off[NN] = carry_s;
}

__global__ void scatter_kernel(const int* __restrict__ ei) {
    int e = blockIdx.x * blockDim.x + threadIdx.x;
    if (e >= ETOT) return;
    int src, dst;
    if (e < NE) { src = ei[e]; dst = ei[NE + e]; }
    else        { src = dst = e - NE; }
    int pos = atomicAdd(&g_cursor[dst], 1);
    g_srcs[pos] = src;
}

// batch is sorted -> binary search graph offsets
__global__ void graph_offsets_kernel(const int* __restrict__ batch) {
    int g = blockIdx.x * blockDim.x + threadIdx.x;
    if (g > NG) return;
    if (g == NG) { g_go[NG] = NN; return; }
    int lo = 0, hi = NN;
    while (lo < hi) {
        int mid = (lo + hi) >> 1;
        if (batch[mid] < g) lo = mid + 1; else hi = mid;
    }
    g_go[g] = lo;
}

// ---------------- GEMM  C[N,M] = A[N,K] @ B[K,M] ----------------
__global__ void gemm_kernel(const float* __restrict__ A, const float* __restrict__ B,
                            float* __restrict__ C, int N, int K, int M) {
    const int BM = 64, BN = 64, BK = 16;
    __shared__ float As[BK][BM + 1];
    __shared__ float Bs[BK][BN];
    int tx = threadIdx.x % 16, ty = threadIdx.x / 16;
    int row0 = blockIdx.y * BM;
    int col0 = blockIdx.x * BN;
    float acc[4][4] = {};
    for (int k0 = 0; k0 < K; k0 += BK) {
        for (int i = threadIdx.x; i < BM * BK; i += 256) {
            int r = i / BK, c = i % BK;
            int gr = row0 + r;
            As[c][r] = (gr < N) ? A[gr * K + k0 + c] : 0.f;
        }
        for (int i = threadIdx.x; i < BK * BN; i += 256) {
            int r = i / BN, c = i % BN;
            int gc = col0 + c;
            Bs[r][c] = (gc < M) ? B[(k0 + r) * M + gc] : 0.f;
        }
        __syncthreads();
#pragma unroll
        for (int k = 0; k < BK; k++) {
            float a[4], b[4];
#pragma unroll
            for (int i = 0; i < 4; i++) a[i] = As[k][ty * 4 + i];
#pragma unroll
            for (int j = 0; j < 4; j++) b[j] = Bs[k][tx * 4 + j];
#pragma unroll
            for (int i = 0; i < 4; i++)
#pragma unroll
                for (int j = 0; j < 4; j++) acc[i][j] += a[i] * b[j];
        }
        __syncthreads();
    }
    for (int i = 0; i < 4; i++) {
        int gr = row0 + ty * 4 + i;
        if (gr >= N) continue;
        for (int j = 0; j < 4; j++) {
            int gc = col0 + tx * 4 + j;
            if (gc < M) C[gr * M + gc] = acc[i][j];
        }
    }
}

// ---------------- GATv2: warp per dst node, online softmax ----------------
// Lane layout: h = lane/8, group-lane g = lane%8, V = (H*C)/32 = C/8 values per lane.
// Row offset for lane's values: lane*V .. lane*V+V-1  (== h*C + g*V).
template <int C, bool MEAN>
__global__ void gat_kernel(const float* __restrict__ xl, const float* __restrict__ xr,
                           const float* __restrict__ att, const float* __restrict__ bias,
                           float* __restrict__ out) {
    constexpr int H = HEADS;
    constexpr int HC = H * C;
    constexpr int V = HC / 32;
    int warp = (blockIdx.x * blockDim.x + threadIdx.x) >> 5;
    int lane = threadIdx.x & 31;
    if (warp >= NN) return;
    int node = warp;

    float attv[V], xrv[V], acc[V];
#pragma unroll
    for (int v = 0; v < V; v++) {
        attv[v] = att[lane * V + v];
        xrv[v]  = xr[node * HC + lane * V + v];
        acc[v]  = 0.f;
    }
    float mrun = -CUDART_INF_F, lrun = 0.f;
    int beg = g_off[node], end = g_off[node + 1];
    for (int j = beg; j < end; j++) {
        int src = g_srcs[j];
        float xlv[V];
        const float* p = xl + (size_t)src * HC + lane * V;
        if (V == 4) {
            float4 t = *reinterpret_cast<const float4*>(p);
            xlv[0] = t.x; xlv[1] = t.y; xlv[V > 2 ? 2 : 0] = t.z; xlv[V > 3 ? 3 : 0] = t.w;
        } else if (V == 2) {
            float2 t = *reinterpret_cast<const float2*>(p);
            xlv[0] = t.x; xlv[V > 1 ? 1 : 0] = t.y;
        } else {
            xlv[0] = p[0];
        }
        float part = 0.f;
#pragma unroll
        for (int v = 0; v < V; v++) {
            float m = xlv[v] + xrv[v];
            m = (m > 0.f) ? m : 0.2f * m;
            part = fmaf(attv[v], m, part);
        }
        part += __shfl_xor_sync(0xffffffffu, part, 1);
        part += __shfl_xor_sync(0xffffffffu, part, 2);
        part += __shfl_xor_sync(0xffffffffu, part, 4);
        float e  = part;
        float nm = fmaxf(mrun, e);
        float sc = __expf(mrun - nm);
        float pw = __expf(e - nm);
#pragma unroll
        for (int v = 0; v < V; v++) acc[v] = fmaf(acc[v], sc, pw * xlv[v]);
        lrun = fmaf(lrun, sc, pw);
        mrun = nm;
    }
    float inv = 1.f / lrun;
    if (!MEAN) {
#pragma unroll
        for (int v = 0; v < V; v++)
            out[(size_t)node * HC + lane * V + v] = acc[v] * inv + bias[lane * V + v];
    } else {
        // V == 1, C == 8: mean over 4 heads, lanes 0..7 write
        float r = acc[0] * inv;
        r += __shfl_xor_sync(0xffffffffu, r, 8);
        r += __shfl_xor_sync(0xffffffffu, r, 16);
        r *= 0.25f;
        if (lane < 8) out[(size_t)node * 8 + lane] = r + bias[lane];
    }
}

// ---------------- GraphNorm + ReLU (block per graph; batch sorted) ----------------
template <int C>
__global__ void graphnorm_relu_kernel(const float* __restrict__ x, float* __restrict__ y,
                                      const float* __restrict__ w, const float* __restrict__ b,
                                      const float* __restrict__ s) {
    constexpr int T = 256;
    constexpr int R = T / C;
    __shared__ float red[T];
    __shared__ float mu[C], rstd[C];
    int g = blockIdx.x;
    int beg = g_go[g], end = g_go[g + 1];
    float fcnt = fmaxf((float)(end - beg), 1.f);
    int t = threadIdx.x;
    int c = t % C, r = t / C;

    float sum = 0.f;
    for (int i = beg + r; i < end; i += R) sum += x[(size_t)i * C + c];
    red[t] = sum; __syncthreads();
    if (t < C) { float v = 0.f; for (int k = t; k < T; k += C) v += red[k]; mu[t] = v / fcnt; }
    __syncthreads();
    float mus = mu[c] * s[c];
    float sq = 0.f;
    for (int i = beg + r; i < end; i += R) { float d = x[(size_t)i * C + c] - mus; sq = fmaf(d, d, sq); }
    __syncthreads();
    red[t] = sq; __syncthreads();
    if (t < C) { float v = 0.f; for (int k = t; k < T; k += C) v += red[k]; rstd[t] = rsqrtf(v / fcnt + 1e-5f); }
    __syncthreads();
    float wc = w[c] * rstd[c], bc = b[c];
    for (int i = beg + r; i < end; i += R) {
        float val = (x[(size_t)i * C + c] - mus) * wc + bc;
        y[(size_t)i * C + c] = val > 0.f ? val : 0.f;
    }
}

// ---------------- pool + linear ----------------
__global__ void pool_linear_kernel(const float* __restrict__ h, const float* __restrict__ lw,
                                   const float* __restrict__ lb, float* __restrict__ out) {
    __shared__ float red[256];
    __shared__ float feat[8];
    int g = blockIdx.x;
    int beg = g_go[g], end = g_go[g + 1];
    float fcnt = fmaxf((float)(end - beg), 1.f);
    int t = threadIdx.x;
    int c = t & 7, r = t >> 3;
    float sum = 0.f;
    for (int i = beg + r; i < end; i += 32) sum += h[(size_t)i * 8 + c];
    red[t] = sum; __syncthreads();
    if (t < 8) { float v = 0.f; for (int k = t; k < 256; k += 8) v += red[k]; feat[t] = v / fcnt; }
    __syncthreads();
    if (t < 8) out[NG * 4 + g * 8 + t] = feat[t];   // features after logits block
    if (t < 4) {
        float v = lb[t];
#pragma unroll
        for (int c2 = 0; c2 < 8; c2++) v = fmaf(feat[c2], lw[c2 * 4 + t], v);
        out[g * 4 + t] = v;                          // logits
    }
}

// ---------------- host orchestration ----------------
static void launch_gemm(const float* A, const float* B, float* C, int N, int K, int M) {
    dim3 grid((M + 63) / 64, (N + 63) / 64);
    gemm_kernel<<<grid, 256>>>(A, B, C, N, K, M);
}

extern "C" void kernel_launch(void* const* d_in, const int* in_sizes, int n_in,
                              void* d_out, int out_size) {
    const float* x     = (const float*)d_in[0];
    const int*   ei    = (const int*)d_in[1];
    const int*   batch = (const int*)d_in[2];
    const float* w_l1 = (const float*)d_in[3];
    const float* w_r1 = (const float*)d_in[4];
    const float* att1 = (const float*)d_in[5];
    const float* b1   = (const float*)d_in[6];
    const float* gn1w = (const float*)d_in[7];
    const float* gn1b = (const float*)d_in[8];
    const float* gn1s = (const float*)d_in[9];
    const float* w_l2 = (const float*)d_in[10];
    const float* w_r2 = (const float*)d_in[11];
    const float* att2 = (const float*)d_in[12];
    const float* b2   = (const float*)d_in[13];
    const float* gn2w = (const float*)d_in[14];
    const float* gn2b = (const float*)d_in[15];
    const float* gn2s = (const float*)d_in[16];
    const float* w_l3 = (const float*)d_in[17];
    const float* w_r3 = (const float*)d_in[18];
    const float* att3 = (const float*)d_in[19];
    const float* b3   = (const float*)d_in[20];
    const float* gn3w = (const float*)d_in[21];
    const float* gn3b = (const float*)d_in[22];
    const float* gn3s = (const float*)d_in[23];
    const float* linw = (const float*)d_in[24];
    const float* linb = (const float*)d_in[25 <= n_in - 1 ? 25 : n_in - 1];
    float* out = (float*)d_out;

    float *xl, *xr, *h1, *h2, *h3;
    cudaGetSymbolAddress((void**)&xl, g_xl);
    cudaGetSymbolAddress((void**)&xr, g_xr);
    cudaGetSymbolAddress((void**)&h1, g_h1);
    cudaGetSymbolAddress((void**)&h2, g_h2);
    cudaGetSymbolAddress((void**)&h3, g_h3);

    // topology
    zero_deg_kernel<<<(NN + 255) / 256, 256>>>();
    count_deg_kernel<<<(ETOT + 255) / 256, 256>>>(ei);
    scan_kernel<<<1, 1024>>>();
    scatter_kernel<<<(ETOT + 255) / 256, 256>>>(ei);
    graph_offsets_kernel<<<1, 128>>>(batch);

    const int GAT_BLOCKS = (NN * 32 + 255) / 256;

    // layer 1: 128 -> 4x32 concat = 128
    launch_gemm(x, w_l1, xl, NN, 128, 128);
    launch_gemm(x, w_r1, xr, NN, 128, 128);
    gat_kernel<32, false><<<GAT_BLOCKS, 256>>>(xl, xr, att1, b1, h1);
    graphnorm_relu_kernel<128><<<NG, 256>>>(h1, h1, gn1w, gn1b, gn1s);

    // layer 2: 128 -> 4x16 concat = 64
    launch_gemm(h1, w_l2, xl, NN, 128, 64);
    launch_gemm(h1, w_r2, xr, NN, 128, 64);
    gat_kernel<16, false><<<GAT_BLOCKS, 256>>>(xl, xr, att2, b2, h2);
    graphnorm_relu_kernel<64><<<NG, 256>>>(h2, h2, gn2w, gn2b, gn2s);

    // layer 3: 64 -> 4x8 mean = 8
    launch_gemm(h2, w_l3, xl, NN, 64, 32);
    launch_gemm(h2, w_r3, xr, NN, 64, 32);
    gat_kernel<8, true><<<GAT_BLOCKS, 256>>>(xl, xr, att3, b3, h3);
    graphnorm_relu_kernel<8><<<NG, 256>>>(h3, h3, gn3w, gn3b, gn3s);

    // pool + linear: out[0:256] logits, out[256:768] features
    pool_linear_kernel<<<NG, 256>>>(h3, linw, linb, out);
}

// round 2
// speedup vs baseline: 1.5088x; 1.5088x over previous
#include <cuda_runtime.h>
#include <cuda_bf16.h>
#include <math_constants.h>

// Problem constants (fixed by the dataset)
#define NN 50000
#define NE 800000
#define ETOT (NE + NN)       // edges + self loops = 850000
#define NG 64
#define HEADS 4
#define NSUB 8               // GraphNorm sub-partitions per graph

// ---------------- scratch (no cudaMalloc allowed) ----------------
__device__ float g_xl[NN * 128];
__device__ float g_xr[NN * 128];
__device__ float g_h1[NN * 128];
__device__ float g_h2[NN * 64];
__device__ float g_h3[NN * 8];
__device__ int   g_deg[NN];
__device__ int   g_off[NN + 1];
__device__ int   g_cursor[NN];
__device__ int   g_srcs[ETOT];
__device__ int   g_go[NG + 1];
__device__ float g_part[NG * NSUB * 2 * 128];
__device__ float g_mus[NG * 128];
__device__ float g_wr[NG * 128];

// ---------------- CSR build ----------------
__global__ void zero_deg_kernel() {
    int i = blockIdx.x * blockDim.x + threadIdx.x;
    if (i < NN) g_deg[i] = 0;
}

__global__ void count_deg_kernel(const int* __restrict__ ei) {
    int e = blockIdx.x * blockDim.x + threadIdx.x;
    if (e >= ETOT) return;
    int dst = (e < NE) ? ei[NE + e] : (e - NE);
    atomicAdd(&g_deg[dst], 1);
}

// single-block exclusive scan (warp-shuffle based)
__global__ void scan_kernel() {
    __shared__ int wsum[32];
    __shared__ int carry_s;
    int t = threadIdx.x, lane = t & 31, wid = t >> 5;
    if (t == 0) carry_s = 0;
    __syncthreads();
    for (int base = 0; base < NN; base += 1024) {
        int i = base + t;
        int v = (i < NN) ? g_deg[i] : 0;
        int s = v;
#pragma unroll
        for (int o = 1; o < 32; o <<= 1) {
            int n = __shfl_up_sync(0xffffffffu, s, o);
            if (lane >= o) s += n;
        }
        if (lane == 31) wsum[wid] = s;
        __syncthreads();
        if (wid == 0) {
            int ws = wsum[lane];
#pragma unroll
            for (int o = 1; o < 32; o <<= 1) {
                int n = __shfl_up_sync(0xffffffffu, ws, o);
                if (lane >= o) ws += n;
            }
            wsum[lane] = ws;
        }
        __syncthreads();
        int carry = carry_s;
        int excl = carry + (wid ? wsum[wid - 1] : 0) + s - v;
        if (i < NN) { g_off[i] = excl; g_cursor[i] = excl; }
        int total = wsum[31];
        __syncthreads();
        if (t == 0) carry_s = carry + total;
        __syncthreads();
    }
    if (t == 0) g_off[NN] = carry_s;
}

__global__ void scatter_kernel(const int* __restrict__ ei) {
    int e = blockIdx.x * blockDim.x + threadIdx.x;
    if (e >= ETOT) return;
    int src, dst;
    if (e < NE) { src = ei[e]; dst = ei[NE + e]; }
    else        { src = dst = e - NE; }
    int pos = atomicAdd(&g_cursor[dst], 1);
    g_srcs[pos] = src;
}

// batch is sorted -> binary search graph offsets
__global__ void graph_offsets_kernel(const int* __restrict__ batch) {
    int g = blockIdx.x * blockDim.x + threadIdx.x;
    if (g > NG) return;
    if (g == NG) { g_go[NG] = NN; return; }
    int lo = 0, hi = NN;
    while (lo < hi) {
        int mid = (lo + hi) >> 1;
        if (batch[mid] < g) lo = mid + 1; else hi = mid;
    }
    g_go[g] = lo;
}

// ---------------- 3xTF32 tensor-core GEMM ----------------
// C[N,M] = A[N,K] @ B[K,M], fp32 in/out, fp32-class accuracy via hi/lo split.
// Block tile: 128 (rows) x 64 (cols), 8 warps, each warp 32x32.
__device__ __forceinline__ unsigned f2tf32(float f) {
    unsigned r;
    asm("cvt.rna.tf32.f32 %0, %1;" : "=r"(r) : "f"(f));
    return r;
}

__device__ __forceinline__ void mma_tf32(float c[4], unsigned a0, unsigned a1,
                                         unsigned a2, unsigned a3,
                                         unsigned b0, unsigned b1) {
    asm volatile(
        "mma.sync.aligned.m16n8k8.row.col.f32.tf32.tf32.f32 "
        "{%0,%1,%2,%3}, {%4,%5,%6,%7}, {%8,%9}, {%0,%1,%2,%3};\n"
        : "+f"(c[0]), "+f"(c[1]), "+f"(c[2]), "+f"(c[3])
        : "r"(a0), "r"(a1), "r"(a2), "r"(a3), "r"(b0), "r"(b1));
}

// gridDim.z == 2: z picks (B0,C0) or (B1,C1) -> fuses the w_l / w_r pair
__global__ __launch_bounds__(256) void gemm_tf32_dual(
    const float* __restrict__ A,
    const float* __restrict__ Bp0, const float* __restrict__ Bp1,
    float* __restrict__ Cp0, float* __restrict__ Cp1,
    int N, int K, int M) {
    const float* B = blockIdx.z ? Bp1 : Bp0;
    float* C = blockIdx.z ? Cp1 : Cp0;

    __shared__ float Ah[128][20], Al[128][20];  // stride 20: conflict-free a-frag
    __shared__ float Bh[16][72],  Bl[16][72];   // stride 72: conflict-free b-frag

    int t = threadIdx.x;
    int w = t >> 5, lane = t & 31;
    int wr = w >> 1, wc = w & 1;            // warp 4x2 grid
    int grp = lane >> 2, tg = lane & 3;
    int row0 = blockIdx.y * 128;
    int col0 = blockIdx.x * 64;

    float c[2][4][4];
#pragma unroll
    for (int i = 0; i < 2; i++)
#pragma unroll
        for (int j = 0; j < 4; j++)
#pragma unroll
            for (int k = 0; k < 4; k++) c[i][j][k] = 0.f;

    for (int k0 = 0; k0 < K; k0 += 16) {
        // load + split A tile (128x16)
#pragma unroll
        for (int i = t; i < 128 * 16; i += 256) {
            int r = i >> 4, cc = i & 15;
            int gr = row0 + r;
            float v = (gr < N) ? A[(size_t)gr * K + k0 + cc] : 0.f;
            unsigned hb = f2tf32(v);
            float hf = __uint_as_float(hb);
            Ah[r][cc] = hf;
            Al[r][cc] = __uint_as_float(f2tf32(v - hf));
        }
        // load + split B tile (16x64)
#pragma unroll
        for (int i = t; i < 16 * 64; i += 256) {
            int r = i >> 6, cc = i & 63;
            int gc = col0 + cc;
            float v = (gc < M) ? B[(size_t)(k0 + r) * M + gc] : 0.f;
            unsigned hb = f2tf32(v);
            float hf = __uint_as_float(hb);
            Bh[r][cc] = hf;
            Bl[r][cc] = __uint_as_float(f2tf32(v - hf));
        }
        __syncthreads();

#pragma unroll
        for (int kk = 0; kk < 16; kk += 8) {
            unsigned ah[2][4], al[2][4];
#pragma unroll
            for (int mt = 0; mt < 2; mt++) {
                int r0 = wr * 32 + mt * 16;
                ah[mt][0] = __float_as_uint(Ah[r0 + grp][kk + tg]);
                ah[mt][1] = __float_as_uint(Ah[r0 + grp + 8][kk + tg]);
                ah[mt][2] = __float_as_uint(Ah[r0 + grp][kk + tg + 4]);
                ah[mt][3] = __float_as_uint(Ah[r0 + grp + 8][kk + tg + 4]);
                al[mt][0] = __float_as_uint(Al[r0 + grp][kk + tg]);
                al[mt][1] = __float_as_uint(Al[r0 + grp + 8][kk + tg]);
                al[mt][2] = __float_as_uint(Al[r0 + grp][kk + tg + 4]);
                al[mt][3] = __float_as_uint(Al[r0 + grp + 8][kk + tg + 4]);
            }
#pragma unroll
            for (int nt = 0; nt < 4; nt++) {
                int ci = wc * 32 + nt * 8 + grp;
                unsigned bh0 = __float_as_uint(Bh[kk + tg][ci]);
                unsigned bh1 = __float_as_uint(Bh[kk + tg + 4][ci]);
                unsigned bl0 = __float_as_uint(Bl[kk + tg][ci]);
                unsigned bl1 = __float_as_uint(Bl[kk + tg + 4][ci]);
#pragma unroll
                for (int mt = 0; mt < 2; mt++) {
                    mma_tf32(c[mt][nt], ah[mt][0], ah[mt][1], ah[mt][2], ah[mt][3], bh0, bh1);
                    mma_tf32(c[mt][nt], al[mt][0], al[mt][1], al[mt][2], al[mt][3], bh0, bh1);
                    mma_tf32(c[mt][nt], ah[mt][0], ah[mt][1], ah[mt][2], ah[mt][3], bl0, bl1);
                }
            }
        }
        __syncthreads();
    }

    // store: c[mt][nt] is 16x8; rows grp/grp+8, cols 2tg/2tg+1
#pragma unroll
    for (int mt = 0; mt < 2; mt++) {
#pragma unroll
        for (int nt = 0; nt < 4; nt++) {
            int gc = col0 + wc * 32 + nt * 8 + 2 * tg;
            if (gc >= M) continue;
            int gr0 = row0 + wr * 32 + mt * 16 + grp;
            if (gr0 < N) {
                float2 v = make_float2(c[mt][nt][0], c[mt][nt][1]);
                *reinterpret_cast<float2*>(C + (size_t)gr0 * M + gc) = v;
            }
            int gr1 = gr0 + 8;
            if (gr1 < N) {
                float2 v = make_float2(c[mt][nt][2], c[mt][nt][3]);
                *reinterpret_cast<float2*>(C + (size_t)gr1 * M + gc) = v;
            }
        }
    }
}

// ---------------- GATv2: warp per dst node, online softmax ----------------
template <int C, bool MEAN>
__global__ void gat_kernel(const float* __restrict__ xl, const float* __restrict__ xr,
                           const float* __restrict__ att, const float* __restrict__ bias,
                           float* __restrict__ out) {
    constexpr int H = HEADS;
    constexpr int HC = H * C;
    constexpr int V = HC / 32;
    int warp = (blockIdx.x * blockDim.x + threadIdx.x) >> 5;
    int lane = threadIdx.x & 31;
    if (warp >= NN) return;
    int node = warp;

    float attv[V], xrv[V], acc[V];
#pragma unroll
    for (int v = 0; v < V; v++) {
        attv[v] = att[lane * V + v];
        xrv[v]  = xr[node * HC + lane * V + v];
        acc[v]  = 0.f;
    }
    float mrun = -CUDART_INF_F, lrun = 0.f;
    int beg = g_off[node], end = g_off[node + 1];
    for (int j = beg; j < end; j++) {
        int src = g_srcs[j];
        float xlv[V];
        const float* p = xl + (size_t)src * HC + lane * V;
        if (V == 4) {
            float4 t = *reinterpret_cast<const float4*>(p);
            xlv[0] = t.x; xlv[1] = t.y; xlv[V > 2 ? 2 : 0] = t.z; xlv[V > 3 ? 3 : 0] = t.w;
        } else if (V == 2) {
            float2 t = *reinterpret_cast<const float2*>(p);
            xlv[0] = t.x; xlv[V > 1 ? 1 : 0] = t.y;
        } else {
            xlv[0] = p[0];
        }
        float part = 0.f;
#pragma unroll
        for (int v = 0; v < V; v++) {
            float m = xlv[v] + xrv[v];
            m = (m > 0.f) ? m : 0.2f * m;
            part = fmaf(attv[v], m, part);
        }
        part += __shfl_xor_sync(0xffffffffu, part, 1);
        part += __shfl_xor_sync(0xffffffffu, part, 2);
        part += __shfl_xor_sync(0xffffffffu, part, 4);
        float e  = part;
        float nm = fmaxf(mrun, e);
        float sc = __expf(mrun - nm);
        float pw = __expf(e - nm);
#pragma unroll
        for (int v = 0; v < V; v++) acc[v] = fmaf(acc[v], sc, pw * xlv[v]);
        lrun = fmaf(lrun, sc, pw);
        mrun = nm;
    }
    float inv = 1.f / lrun;
    if (!MEAN) {
#pragma unroll
        for (int v = 0; v < V; v++)
            out[(size_t)node * HC + lane * V + v] = acc[v] * inv + bias[lane * V + v];
    } else {
        float r = acc[0] * inv;
        r += __shfl_xor_sync(0xffffffffu, r, 8);
        r += __shfl_xor_sync(0xffffffffu, r, 16);
        r *= 0.25f;
        if (lane < 8) out[(size_t)node * 8 + lane] = r + bias[lane];
    }
}

// ---------------- GraphNorm (3-kernel, full-grid, deterministic) ----------------
// var = E[(x - mus)^2] = E[x^2] - 2*mus*E[x] + mus^2
template <int C>
__global__ void gn_part_kernel(const float* __restrict__ x) {
    constexpr int R = 256 / C;
    __shared__ float red[256], red2[256];
    int g = blockIdx.x, sub = blockIdx.y;
    int beg = g_go[g], end = g_go[g + 1];
    int t = threadIdx.x, c = t % C, r = t / C;
    float s = 0.f, q = 0.f;
    for (int i = beg + sub * R + r; i < end; i += NSUB * R) {
        float v = x[(size_t)i * C + c];
        s += v; q = fmaf(v, v, q);
    }
    red[t] = s; red2[t] = q;
    __syncthreads();
    if (t < C) {
        float ss = 0.f, qq = 0.f;
        for (int k = t; k < 256; k += C) { ss += red[k]; qq += red2[k]; }
        g_part[(g * NSUB + sub) * 2 * C + t] = ss;
        g_part[(g * NSUB + sub) * 2 * C + C + t] = qq;
    }
}

template <int C>
__global__ void gn_final_kernel(const float* __restrict__ w, const float* __restrict__ sc) {
    int g = blockIdx.x, c = threadIdx.x;
    int beg = g_go[g], end = g_go[g + 1];
    float cnt = fmaxf((float)(end - beg), 1.f);
    float s = 0.f, q = 0.f;
    for (int sub = 0; sub < NSUB; sub++) {
        s += g_part[(g * NSUB + sub) * 2 * C + c];
        q += g_part[(g * NSUB + sub) * 2 * C + C + c];
    }
    float mu = s / cnt;
    float mus = mu * sc[c];
    float var = q / cnt - 2.f * mus * mu + mus * mus;
    g_mus[g * C + c] = mus;
    g_wr[g * C + c] = w[c] * rsqrtf(var + 1e-5f);
}

template <int C>
__global__ void gn_norm_kernel(const float* __restrict__ x, float* __restrict__ y,
                               const float* __restrict__ b, const int* __restrict__ batch) {
    int i4 = blockIdx.x * blockDim.x + threadIdx.x;
    if (i4 >= NN * C / 4) return;
    int idx = i4 * 4;
    int node = idx / C, c = idx % C;
    int g = batch[node];
    float4 xv = *reinterpret_cast<const float4*>(x + idx);
    float4 mv = *reinterpret_cast<const float4*>(g_mus + g * C + c);
    float4 wv = *reinterpret_cast<const float4*>(g_wr + g * C + c);
    float4 bv = *reinterpret_cast<const float4*>(b + c);
    float4 o;
    o.x = fmaxf(fmaf(xv.x - mv.x, wv.x, bv.x), 0.f);
    o.y = fmaxf(fmaf(xv.y - mv.y, wv.y, bv.y), 0.f);
    o.z = fmaxf(fmaf(xv.z - mv.z, wv.z, bv.z), 0.f);
    o.w = fmaxf(fmaf(xv.w - mv.w, wv.w, bv.w), 0.f);
    *reinterpret_cast<float4*>(y + idx) = o;
}

// ---------------- pool + linear ----------------
__global__ void pool_linear_kernel(const float* __restrict__ h, const float* __restrict__ lw,
                                   const float* __restrict__ lb, float* __restrict__ out) {
    __shared__ float red[256];
    __shared__ float feat[8];
    int g = blockIdx.x;
    int beg = g_go[g], end = g_go[g + 1];
    float fcnt = fmaxf((float)(end - beg), 1.f);
    int t = threadIdx.x;
    int c = t & 7, r = t >> 3;
    float sum = 0.f;
    for (int i = beg + r; i < end; i += 32) sum += h[(size_t)i * 8 + c];
    red[t] = sum; __syncthreads();
    if (t < 8) { float v = 0.f; for (int k = t; k < 256; k += 8) v += red[k]; feat[t] = v / fcnt; }
    __syncthreads();
    if (t < 8) out[NG * 4 + g * 8 + t] = feat[t];   // features after logits block
    if (t < 4) {
        float v = lb[t];
#pragma unroll
        for (int c2 = 0; c2 < 8; c2++) v = fmaf(feat[c2], lw[c2 * 4 + t], v);
        out[g * 4 + t] = v;                          // logits
    }
}

// ---------------- host orchestration ----------------
static void launch_gemm_dual(const float* A, const float* B0, const float* B1,
                             float* C0, float* C1, int N, int K, int M) {
    dim3 grid((M + 63) / 64, (N + 127) / 128, 2);
    gemm_tf32_dual<<<grid, 256>>>(A, B0, B1, C0, C1, N, K, M);
}

template <int C>
static void launch_graphnorm(const float* x, float* y, const float* w, const float* b,
                             const float* s, const int* batch) {
    gn_part_kernel<C><<<dim3(NG, NSUB), 256>>>(x);
    gn_final_kernel<C><<<NG, C>>>(w, s);
    gn_norm_kernel<C><<<(NN * C / 4 + 255) / 256, 256>>>(x, y, b, batch);
}

extern "C" void kernel_launch(void* const* d_in, const int* in_sizes, int n_in,
                              void* d_out, int out_size) {
    const float* x     = (const float*)d_in[0];
    const int*   ei    = (const int*)d_in[1];
    const int*   batch = (const int*)d_in[2];
    const float* w_l1 = (const float*)d_in[3];
    const float* w_r1 = (const float*)d_in[4];
    const float* att1 = (const float*)d_in[5];
    const float* b1   = (const float*)d_in[6];
    const float* gn1w = (const float*)d_in[7];
    const float* gn1b = (const float*)d_in[8];
    const float* gn1s = (const float*)d_in[9];
    const float* w_l2 = (const float*)d_in[10];
    const float* w_r2 = (const float*)d_in[11];
    const float* att2 = (const float*)d_in[12];
    const float* b2   = (const float*)d_in[13];
    const float* gn2w = (const float*)d_in[14];
    const float* gn2b = (const float*)d_in[15];
    const float* gn2s = (const float*)d_in[16];
    const float* w_l3 = (const float*)d_in[17];
    const float* w_r3 = (const float*)d_in[18];
    const float* att3 = (const float*)d_in[19];
    const float* b3   = (const float*)d_in[20];
    const float* gn3w = (const float*)d_in[21];
    const float* gn3b = (const float*)d_in[22];
    const float* gn3s = (const float*)d_in[23];
    const float* linw = (const float*)d_in[24];
    const float* linb = (const float*)d_in[25];
    float* out = (float*)d_out;

    float *xl, *xr, *h1, *h2, *h3;
    cudaGetSymbolAddress((void**)&xl, g_xl);
    cudaGetSymbolAddress((void**)&xr, g_xr);
    cudaGetSymbolAddress((void**)&h1, g_h1);
    cudaGetSymbolAddress((void**)&h2, g_h2);
    cudaGetSymbolAddress((void**)&h3, g_h3);

    // topology
    zero_deg_kernel<<<(NN + 255) / 256, 256>>>();
    count_deg_kernel<<<(ETOT + 255) / 256, 256>>>(ei);
    scan_kernel<<<1, 1024>>>();
    scatter_kernel<<<(ETOT + 255) / 256, 256>>>(ei);
    graph_offsets_kernel<<<1, 128>>>(batch);

    const int GAT_BLOCKS = (NN * 32 + 255) / 256;

    // layer 1: 128 -> 4x32 concat = 128
    launch_gemm_dual(x, w_l1, w_r1, xl, xr, NN, 128, 128);
    gat_kernel<32, false><<<GAT_BLOCKS, 256>>>(xl, xr, att1, b1, h1);
    launch_graphnorm<128>(h1, h1, gn1w, gn1b, gn1s, batch);

    // layer 2: 128 -> 4x16 concat = 64
    launch_gemm_dual(h1, w_l2, w_r2, xl, xr, NN, 128, 64);
    gat_kernel<16, false><<<GAT_BLOCKS, 256>>>(xl, xr, att2, b2, h2);
    launch_graphnorm<64>(h2, h2, gn2w, gn2b, gn2s, batch);

    // layer 3: 64 -> 4x8 mean = 8
    launch_gemm_dual(h2, w_l3, w_r3, xl, xr, NN, 64, 32);
    gat_kernel<8, true><<<GAT_BLOCKS, 256>>>(xl, xr, att3, b3, h3);
    launch_graphnorm<8>(h3, h3, gn3w, gn3b, gn3s, batch);

    // pool + linear: out[0:256] logits, out[256:768] features
    pool_linear_kernel<<<NG, 256>>>(h3, linw, linb, out);
}

// round 3
// speedup vs baseline: 1.6577x; 1.0987x over previous
#include <cuda_runtime.h>
#include <cuda_bf16.h>
#include <math_constants.h>

// Problem constants (fixed by the dataset)
#define NN 50000
#define NE 800000
#define ETOT (NE + NN)       // edges + self loops = 850000
#define NG 64
#define HEADS 4
#define NSUB 8               // GraphNorm sub-partitions per graph

// ---------------- scratch (no cudaMalloc allowed) ----------------
__device__ float g_xl[NN * 128];
__device__ float g_xr[NN * 128];
__device__ float g_h1[NN * 128];
__device__ float g_h2[NN * 64];
__device__ float g_h3[NN * 8];
__device__ int   g_deg[NN];
__device__ int   g_off[NN + 1];
__device__ int   g_cursor[NN];
__device__ int   g_srcs[ETOT];
__device__ int   g_go[NG + 1];
__device__ float g_part[NG * NSUB * 2 * 128];
__device__ float g_mus[NG * 128];
__device__ float g_wr[NG * 128];

// ---------------- cp.async helpers ----------------
__device__ __forceinline__ void cp_async16(void* smem_ptr, const void* gmem_ptr, bool pred) {
    unsigned saddr = (unsigned)__cvta_generic_to_shared(smem_ptr);
    int sz = pred ? 16 : 0;
    asm volatile("cp.async.ca.shared.global [%0], [%1], 16, %2;\n"
                 :: "r"(saddr), "l"(gmem_ptr), "r"(sz));
}
__device__ __forceinline__ void cp_commit() { asm volatile("cp.async.commit_group;\n"); }
template <int N>
__device__ __forceinline__ void cp_wait() { asm volatile("cp.async.wait_group %0;\n" :: "n"(N)); }

// ---------------- CSR build ----------------
__global__ void zero_deg_kernel() {
    int i = blockIdx.x * blockDim.x + threadIdx.x;
    if (i < NN) g_deg[i] = 0;
}

__global__ void count_deg_kernel(const int* __restrict__ ei) {
    int e = blockIdx.x * blockDim.x + threadIdx.x;
    if (e >= ETOT) return;
    int dst = (e < NE) ? ei[NE + e] : (e - NE);
    atomicAdd(&g_deg[dst], 1);
}

// single-block exclusive scan (warp-shuffle based) + graph offsets
__global__ void scan_kernel(const int* __restrict__ batch) {
    __shared__ int wsum[32];
    __shared__ int carry_s;
    int t = threadIdx.x, lane = t & 31, wid = t >> 5;
    if (t == 0) carry_s = 0;
    __syncthreads();
    for (int base = 0; base < NN; base += 1024) {
        int i = base + t;
        int v = (i < NN) ? g_deg[i] : 0;
        int s = v;
#pragma unroll
        for (int o = 1; o < 32; o <<= 1) {
            int n = __shfl_up_sync(0xffffffffu, s, o);
            if (lane >= o) s += n;
        }
        if (lane == 31) wsum[wid] = s;
        __syncthreads();
        if (wid == 0) {
            int ws = wsum[lane];
#pragma unroll
            for (int o = 1; o < 32; o <<= 1) {
                int n = __shfl_up_sync(0xffffffffu, ws, o);
                if (lane >= o) ws += n;
            }
            wsum[lane] = ws;
        }
        __syncthreads();
        int carry = carry_s;
        int excl = carry + (wid ? wsum[wid - 1] : 0) + s - v;
        if (i < NN) { g_off[i] = excl; g_cursor[i] = excl; }
        int total = wsum[31];
        __syncthreads();
        if (t == 0) carry_s = carry + total;
        __syncthreads();
    }
    if (t == 0) g_off[NN] = carry_s;
    // fused graph offsets (batch is sorted)
    if (t <= NG) {
        if (t == NG) g_go[NG] = NN;
        else {
            int lo = 0, hi = NN;
            while (lo < hi) {
                int mid = (lo + hi) >> 1;
                if (batch[mid] < t) lo = mid + 1; else hi = mid;
            }
            g_go[t] = lo;
        }
    }
}

__global__ void scatter_kernel(const int* __restrict__ ei) {
    int e = blockIdx.x * blockDim.x + threadIdx.x;
    if (e >= ETOT) return;
    int src, dst;
    if (e < NE) { src = ei[e]; dst = ei[NE + e]; }
    else        { src = dst = e - NE; }
    int pos = atomicAdd(&g_cursor[dst], 1);
    g_srcs[pos] = src;
}

// ---------------- 3xTF32 tensor-core GEMM v2 ----------------
// C[N,M] = A[N,K] @ B[K,M], fp32 in/out, fp32-class accuracy via hi/lo split.
// Raw fp32 tiles in smem (split at fragment load), cp.async double buffer.
// Block tile: 128 x 64, 8 warps (4x2), each warp 32x32.
__device__ __forceinline__ unsigned f2tf32(float f) {
    unsigned r;
    asm("cvt.rna.tf32.f32 %0, %1;" : "=r"(r) : "f"(f));
    return r;
}
__device__ __forceinline__ void split_tf32(float v, unsigned& hi, unsigned& lo) {
    hi = f2tf32(v);
    lo = f2tf32(v - __uint_as_float(hi));
}
__device__ __forceinline__ void mma_tf32(float c[4], unsigned a0, unsigned a1,
                                         unsigned a2, unsigned a3,
                                         unsigned b0, unsigned b1) {
    asm volatile(
        "mma.sync.aligned.m16n8k8.row.col.f32.tf32.tf32.f32 "
        "{%0,%1,%2,%3}, {%4,%5,%6,%7}, {%8,%9}, {%0,%1,%2,%3};\n"
        : "+f"(c[0]), "+f"(c[1]), "+f"(c[2]), "+f"(c[3])
        : "r"(a0), "r"(a1), "r"(a2), "r"(a3), "r"(b0), "r"(b1));
}

__global__ __launch_bounds__(256) void gemm_tf32_dual(
    const float* __restrict__ A,
    const float* __restrict__ Bp0, const float* __restrict__ Bp1,
    float* __restrict__ Cp0, float* __restrict__ Cp1,
    int N, int K, int M) {
    const float* B = blockIdx.z ? Bp1 : Bp0;
    float* C = blockIdx.z ? Cp1 : Cp0;

    __shared__ float As[2][128][20];  // stride 20: conflict-free a-frag LDS
    __shared__ float Bs[2][16][72];   // stride 72: conflict-free b-frag LDS

    int t = threadIdx.x;
    int w = t >> 5, lane = t & 31;
    int wr = w >> 1, wc = w & 1;
    int grp = lane >> 2, tg = lane & 3;
    int row0 = blockIdx.y * 128;
    int col0 = blockIdx.x * 64;

    float c[2][4][4];
#pragma unroll
    for (int i = 0; i < 2; i++)
#pragma unroll
        for (int j = 0; j < 4; j++)
#pragma unroll
            for (int k = 0; k < 4; k++) c[i][j][k] = 0.f;

    auto load_tiles = [&](int stage, int k0) {
        // A tile 128x16 = 512 float4, 2 per thread
#pragma unroll
        for (int i = t; i < 512; i += 256) {
            int r = i >> 2, c4 = (i & 3) * 4;
            bool p = (row0 + r) < N;
            const float* src = p ? (A + (size_t)(row0 + r) * K + k0 + c4) : A;
            cp_async16(&As[stage][r][c4], src, p);
        }
        // B tile 16x64 = 256 float4, 1 per thread
        {
            int r = t >> 4, c4 = (t & 15) * 4;
            bool p = (col0 + c4) < M;
            const float* src = p ? (B + (size_t)(k0 + r) * M + col0 + c4) : B;
            cp_async16(&Bs[stage][r][c4], src, p);
        }
    };

    int KT = K >> 4;
    load_tiles(0, 0);
    cp_commit();

    for (int kt = 0; kt < KT; kt++) {
        int cur = kt & 1;
        if (kt + 1 < KT) {
            load_tiles(cur ^ 1, (kt + 1) << 4);
            cp_commit();
            cp_wait<1>();
        } else {
            cp_wait<0>();
        }
        __syncthreads();

#pragma unroll
        for (int kk = 0; kk < 16; kk += 8) {
            unsigned ah[2][4], al[2][4];
#pragma unroll
            for (int mt = 0; mt < 2; mt++) {
                int r0 = wr * 32 + mt * 16;
                float a0 = As[cur][r0 + grp][kk + tg];
                float a1 = As[cur][r0 + grp + 8][kk + tg];
                float a2 = As[cur][r0 + grp][kk + tg + 4];
                float a3 = As[cur][r0 + grp + 8][kk + tg + 4];
                split_tf32(a0, ah[mt][0], al[mt][0]);
                split_tf32(a1, ah[mt][1], al[mt][1]);
                split_tf32(a2, ah[mt][2], al[mt][2]);
                split_tf32(a3, ah[mt][3], al[mt][3]);
            }
#pragma unroll
            for (int nt = 0; nt < 4; nt++) {
                int ci = wc * 32 + nt * 8 + grp;
                float b0 = Bs[cur][kk + tg][ci];
                float b1 = Bs[cur][kk + tg + 4][ci];
                unsigned bh0, bl0, bh1, bl1;
                split_tf32(b0, bh0, bl0);
                split_tf32(b1, bh1, bl1);
#pragma unroll
                for (int mt = 0; mt < 2; mt++) {
                    mma_tf32(c[mt][nt], ah[mt][0], ah[mt][1], ah[mt][2], ah[mt][3], bh0, bh1);
                    mma_tf32(c[mt][nt], al[mt][0], al[mt][1], al[mt][2], al[mt][3], bh0, bh1);
                    mma_tf32(c[mt][nt], ah[mt][0], ah[mt][1], ah[mt][2], ah[mt][3], bl0, bl1);
                }
            }
        }
        __syncthreads();
    }

    // store: c[mt][nt] is 16x8; rows grp/grp+8, cols 2tg/2tg+1
#pragma unroll
    for (int mt = 0; mt < 2; mt++) {
#pragma unroll
        for (int nt = 0; nt < 4; nt++) {
            int gc = col0 + wc * 32 + nt * 8 + 2 * tg;
            if (gc >= M) continue;
            int gr0 = row0 + wr * 32 + mt * 16 + grp;
            if (gr0 < N) {
                float2 v = make_float2(c[mt][nt][0], c[mt][nt][1]);
                *reinterpret_cast<float2*>(C + (size_t)gr0 * M + gc) = v;
            }
            int gr1 = gr0 + 8;
            if (gr1 < N) {
                float2 v = make_float2(c[mt][nt][2], c[mt][nt][3]);
                *reinterpret_cast<float2*>(C + (size_t)gr1 * M + gc) = v;
            }
        }
    }
}

// ---------------- GATv2: warp per dst node, online softmax, prefetch ----------------
template <int V>
__device__ __forceinline__ void load_row(float* d, const float* p) {
    if (V == 4) {
        float4 t = *reinterpret_cast<const float4*>(p);
        d[0] = t.x; d[1] = t.y; d[V > 2 ? 2 : 0] = t.z; d[V > 3 ? 3 : 0] = t.w;
    } else if (V == 2) {
        float2 t = *reinterpret_cast<const float2*>(p);
        d[0] = t.x; d[V > 1 ? 1 : 0] = t.y;
    } else {
        d[0] = p[0];
    }
}

template <int C, bool MEAN>
__global__ void gat_kernel(const float* __restrict__ xl, const float* __restrict__ xr,
                           const float* __restrict__ att, const float* __restrict__ bias,
                           float* __restrict__ out) {
    constexpr int H = HEADS;
    constexpr int HC = H * C;
    constexpr int V = HC / 32;
    int warp = (blockIdx.x * blockDim.x + threadIdx.x) >> 5;
    int lane = threadIdx.x & 31;
    if (warp >= NN) return;
    int node = warp;

    float attv[V], xrv[V], acc[V];
#pragma unroll
    for (int v = 0; v < V; v++) {
        attv[v] = att[lane * V + v];
        xrv[v]  = xr[node * HC + lane * V + v];
        acc[v]  = 0.f;
    }
    float mrun = -CUDART_INF_F, lrun = 0.f;
    int beg = g_off[node], end = g_off[node + 1];

    // software pipeline: prefetch next src row while computing current
    float nxt[V];
    load_row<V>(nxt, xl + (size_t)g_srcs[beg] * HC + lane * V);
    for (int j = beg; j < end; j++) {
        float cur[V];
#pragma unroll
        for (int v = 0; v < V; v++) cur[v] = nxt[v];
        if (j + 1 < end) {
            int ns = g_srcs[j + 1];
            load_row<V>(nxt, xl + (size_t)ns * HC + lane * V);
        }
        float part = 0.f;
#pragma unroll
        for (int v = 0; v < V; v++) {
            float m = cur[v] + xrv[v];
            m = (m > 0.f) ? m : 0.2f * m;
            part = fmaf(attv[v], m, part);
        }
        part += __shfl_xor_sync(0xffffffffu, part, 1);
        part += __shfl_xor_sync(0xffffffffu, part, 2);
        part += __shfl_xor_sync(0xffffffffu, part, 4);
        float e  = part;
        float nm = fmaxf(mrun, e);
        float sc = __expf(mrun - nm);
        float pw = __expf(e - nm);
#pragma unroll
        for (int v = 0; v < V; v++) acc[v] = fmaf(acc[v], sc, pw * cur[v]);
        lrun = fmaf(lrun, sc, pw);
        mrun = nm;
    }
    float inv = 1.f / lrun;
    if (!MEAN) {
#pragma unroll
        for (int v = 0; v < V; v++)
            out[(size_t)node * HC + lane * V + v] = acc[v] * inv + bias[lane * V + v];
    } else {
        float r = acc[0] * inv;
        r += __shfl_xor_sync(0xffffffffu, r, 8);
        r += __shfl_xor_sync(0xffffffffu, r, 16);
        r *= 0.25f;
        if (lane < 8) out[(size_t)node * 8 + lane] = r + bias[lane];
    }
}

// ---------------- GraphNorm (3-kernel, full-grid, deterministic) ----------------
template <int C>
__global__ void gn_part_kernel(const float* __restrict__ x) {
    constexpr int R = 256 / C;
    __shared__ float red[256], red2[256];
    int g = blockIdx.x, sub = blockIdx.y;
    int beg = g_go[g], end = g_go[g + 1];
    int t = threadIdx.x, c = t % C, r = t / C;
    float s = 0.f, q = 0.f;
    for (int i = beg + sub * R + r; i < end; i += NSUB * R) {
        float v = x[(size_t)i * C + c];
        s += v; q = fmaf(v, v, q);
    }
    red[t] = s; red2[t] = q;
    __syncthreads();
    if (t < C) {
        float ss = 0.f, qq = 0.f;
        for (int k = t; k < 256; k += C) { ss += red[k]; qq += red2[k]; }
        g_part[(g * NSUB + sub) * 2 * C + t] = ss;
        g_part[(g * NSUB + sub) * 2 * C + C + t] = qq;
    }
}

template <int C>
__global__ void gn_final_kernel(const float* __restrict__ w, const float* __restrict__ sc) {
    int g = blockIdx.x, c = threadIdx.x;
    int beg = g_go[g], end = g_go[g + 1];
    float cnt = fmaxf((float)(end - beg), 1.f);
    float s = 0.f, q = 0.f;
    for (int sub = 0; sub < NSUB; sub++) {
        s += g_part[(g * NSUB + sub) * 2 * C + c];
        q += g_part[(g * NSUB + sub) * 2 * C + C + c];
    }
    float mu = s / cnt;
    float mus = mu * sc[c];
    float var = q / cnt - 2.f * mus * mu + mus * mus;
    g_mus[g * C + c] = mus;
    g_wr[g * C + c] = w[c] * rsqrtf(var + 1e-5f);
}

template <int C>
__global__ void gn_norm_kernel(const float* __restrict__ x, float* __restrict__ y,
                               const float* __restrict__ b, const int* __restrict__ batch) {
    int i4 = blockIdx.x * blockDim.x + threadIdx.x;
    if (i4 >= NN * C / 4) return;
    int idx = i4 * 4;
    int node = idx / C, c = idx % C;
    int g = batch[node];
    float4 xv = *reinterpret_cast<const float4*>(x + idx);
    float4 mv = *reinterpret_cast<const float4*>(g_mus + g * C + c);
    float4 wv = *reinterpret_cast<const float4*>(g_wr + g * C + c);
    float4 bv = *reinterpret_cast<const float4*>(b + c);
    float4 o;
    o.x = fmaxf(fmaf(xv.x - mv.x, wv.x, bv.x), 0.f);
    o.y = fmaxf(fmaf(xv.y - mv.y, wv.y, bv.y), 0.f);
    o.z = fmaxf(fmaf(xv.z - mv.z, wv.z, bv.z), 0.f);
    o.w = fmaxf(fmaf(xv.w - mv.w, wv.w, bv.w), 0.f);
    *reinterpret_cast<float4*>(y + idx) = o;
}

// ---------------- pool + linear ----------------
__global__ void pool_linear_kernel(const float* __restrict__ h, const float* __restrict__ lw,
                                   const float* __restrict__ lb, float* __restrict__ out) {
    __shared__ float red[256];
    __shared__ float feat[8];
    int g = blockIdx.x;
    int beg = g_go[g], end = g_go[g + 1];
    float fcnt = fmaxf((float)(end - beg), 1.f);
    int t = threadIdx.x;
    int c = t & 7, r = t >> 3;
    float sum = 0.f;
    for (int i = beg + r; i < end; i += 32) sum += h[(size_t)i * 8 + c];
    red[t] = sum; __syncthreads();
    if (t < 8) { float v = 0.f; for (int k = t; k < 256; k += 8) v += red[k]; feat[t] = v / fcnt; }
    __syncthreads();
    if (t < 8) out[NG * 4 + g * 8 + t] = feat[t];   // features after logits block
    if (t < 4) {
        float v = lb[t];
#pragma unroll
        for (int c2 = 0; c2 < 8; c2++) v = fmaf(feat[c2], lw[c2 * 4 + t], v);
        out[g * 4 + t] = v;                          // logits
    }
}

// ---------------- host orchestration ----------------
static void launch_gemm_dual(const float* A, const float* B0, const float* B1,
                             float* C0, float* C1, int N, int K, int M) {
    dim3 grid((M + 63) / 64, (N + 127) / 128, 2);
    gemm_tf32_dual<<<grid, 256>>>(A, B0, B1, C0, C1, N, K, M);
}

template <int C>
static void launch_graphnorm(const float* x, float* y, const float* w, const float* b,
                             const float* s, const int* batch) {
    gn_part_kernel<C><<<dim3(NG, NSUB), 256>>>(x);
    gn_final_kernel<C><<<NG, C>>>(w, s);
    gn_norm_kernel<C><<<(NN * C / 4 + 255) / 256, 256>>>(x, y, b, batch);
}

extern "C" void kernel_launch(void* const* d_in, const int* in_sizes, int n_in,
                              void* d_out, int out_size) {
    const float* x     = (const float*)d_in[0];
    const int*   ei    = (const int*)d_in[1];
    const int*   batch = (const int*)d_in[2];
    const float* w_l1 = (const float*)d_in[3];
    const float* w_r1 = (const float*)d_in[4];
    const float* att1 = (const float*)d_in[5];
    const float* b1   = (const float*)d_in[6];
    const float* gn1w = (const float*)d_in[7];
    const float* gn1b = (const float*)d_in[8];
    const float* gn1s = (const float*)d_in[9];
    const float* w_l2 = (const float*)d_in[10];
    const float* w_r2 = (const float*)d_in[11];
    const float* att2 = (const float*)d_in[12];
    const float* b2   = (const float*)d_in[13];
    const float* gn2w = (const float*)d_in[14];
    const float* gn2b = (const float*)d_in[15];
    const float* gn2s = (const float*)d_in[16];
    const float* w_l3 = (const float*)d_in[17];
    const float* w_r3 = (const float*)d_in[18];
    const float* att3 = (const float*)d_in[19];
    const float* b3   = (const float*)d_in[20];
    const float* gn3w = (const float*)d_in[21];
    const float* gn3b = (const float*)d_in[22];
    const float* gn3s = (const float*)d_in[23];
    const float* linw = (const float*)d_in[24];
    const float* linb = (const float*)d_in[25];
    float* out = (float*)d_out;

    float *xl, *xr, *h1, *h2, *h3;
    cudaGetSymbolAddress((void**)&xl, g_xl);
    cudaGetSymbolAddress((void**)&xr, g_xr);
    cudaGetSymbolAddress((void**)&h1, g_h1);
    cudaGetSymbolAddress((void**)&h2, g_h2);
    cudaGetSymbolAddress((void**)&h3, g_h3);

    // topology (gemm1 interleaved so it lands on the ncu capture slot)
    zero_deg_kernel<<<(NN + 255) / 256, 256>>>();                 // launch 0
    count_deg_kernel<<<(ETOT + 255) / 256, 256>>>(ei);            // launch 1
    scan_kernel<<<1, 1024>>>(batch);                              // launch 2

    // layer 1 GEMM (independent of CSR) — launch 3 = ncu capture target
    launch_gemm_dual(x, w_l1, w_r1, xl, xr, NN, 128, 128);

    scatter_kernel<<<(ETOT + 255) / 256, 256>>>(ei);              // launch 4

    const int GAT_BLOCKS = (NN * 32 + 255) / 256;

    // layer 1: 128 -> 4x32 concat = 128
    gat_kernel<32, false><<<GAT_BLOCKS, 256>>>(xl, xr, att1, b1, h1);
    launch_graphnorm<128>(h1, h1, gn1w, gn1b, gn1s, batch);

    // layer 2: 128 -> 4x16 concat = 64
    launch_gemm_dual(h1, w_l2, w_r2, xl, xr, NN, 128, 64);
    gat_kernel<16, false><<<GAT_BLOCKS, 256>>>(xl, xr, att2, b2, h2);
    launch_graphnorm<64>(h2, h2, gn2w, gn2b, gn2s, batch);

    // layer 3: 64 -> 4x8 mean = 8
    launch_gemm_dual(h2, w_l3, w_r3, xl, xr, NN, 64, 32);
    gat_kernel<8, true><<<GAT_BLOCKS, 256>>>(xl, xr, att3, b3, h3);
    launch_graphnorm<8>(h3, h3, gn3w, gn3b, gn3s, batch);

    // pool + linear: out[0:256] logits, out[256:768] features
    pool_linear_kernel<<<NG, 256>>>(h3, linw, linb, out);
}